// round 16
// baseline (speedup 1.0000x reference)
#include <cuda_runtime.h>
#include <math.h>

#define Bn 64
#define Tn 512
#define En 512
#define Hn 512
#define Kn 12
#define STARTT 10
#define STOPT 11
#define NEGV (-10000.0f)

// ---------------- scratch (device globals; allocation-free rule) ----------------
__device__ float g_pre[2][32768 * 2048];      // [dir][(b*512+t)*2048 + gate*512+j]
__device__ int   g_tok[2][32768];             // [dir][b*512+t]
__device__ float g_h[2][2][Bn * Hn];          // [phase][dir][b*512+j]
__device__ float g_c[2][Bn * Hn];             // [dir][b*512+j]
__device__ float g_outH[33554432];            // [(b*512+t)*1024 + dir*512+j]
__device__ float g_feats[Bn * Tn * Kn];
__device__ signed char g_bp[Bn * Tn * Kn];
__device__ unsigned g_ctrs[2][Tn];            // per-(dir,step) arrival counters

// ---------------- init ----------------
__global__ void k_init(const float* __restrict__ h0, const float* __restrict__ c0) {
    int i = blockIdx.x * 256 + threadIdx.x;
    if (i < 2 * Tn) ((unsigned*)g_ctrs)[i] = 0u;
    if (i < 2 * Bn * Hn) {
        int d = i / (Bn * Hn), r = i % (Bn * Hn);
        g_h[0][d][r] = h0[i];
        g_c[d][r]    = c0[i];
    }
}

// ---------------- token build (forward + packed-reversed; 0 in padding) ----------------
__global__ void k_tok(const int* __restrict__ sent, const int* __restrict__ seq) {
    int i = blockIdx.x * 256 + threadIdx.x;
    if (i >= 2 * 32768) return;
    int d = i >> 15, r = i & 32767, b = r >> 9, t = r & 511;
    int L = seq[b];
    int tk = 0;
    if (t < L) tk = (d == 0) ? sent[b * Tn + t] : sent[b * Tn + (L - 1 - t)];
    g_tok[d][r] = tk;
}

// ---------------- TF32 helpers ----------------
__device__ __forceinline__ unsigned tf32r(float v) {
    unsigned u;
    asm("cvt.rna.tf32.f32 %0, %1;" : "=r"(u) : "f"(v));
    return u;
}
#define MMA_TF32(c, A, B0, B1)                                                  \
    asm volatile("mma.sync.aligned.m16n8k8.row.col.f32.tf32.tf32.f32 "          \
                 "{%0,%1,%2,%3},{%4,%5,%6,%7},{%8,%9},{%0,%1,%2,%3};"           \
                 : "+f"((c)[0]), "+f"((c)[1]), "+f"((c)[2]), "+f"((c)[3])       \
                 : "r"((A).x), "r"((A).y), "r"((A).z), "r"((A).w),              \
                   "r"(B0), "r"(B1))

// packed f32x2 ops
#define FMA2(acc, a, b) \
    asm("fma.rn.f32x2 %0, %1, %2, %0;" : "+l"(acc) : "l"(a), "l"(b))
#define ADD2(r, a, b) \
    asm("add.rn.f32x2 %0, %1, %2;" : "=l"(r) : "l"(a), "l"(b))

__device__ __forceinline__ float fold2(unsigned long long v) {
    return __uint_as_float((unsigned)(v & 0xffffffffu)) +
           __uint_as_float((unsigned)(v >> 32));
}
__device__ __forceinline__ unsigned long long pack2(float lo, float hi) {
    unsigned long long r;
    asm("mov.b64 %0, {%1,%2};" : "=l"(r) : "r"(__float_as_uint(lo)), "r"(__float_as_uint(hi)));
    return r;
}
__device__ __forceinline__ float sigf(float x) {
    return __fdividef(1.f, 1.f + __expf(-x));
}
__device__ __forceinline__ float tanhfa(float x) {
    return 2.f * __fdividef(1.f, 1.f + __expf(-2.f * x)) - 1.f;
}

// ---------------- input GEMM (TF32 tensor cores): pre = gather(embed, tok) @ Wi^T ----
__global__ void __launch_bounds__(256) k_gemm(
    const float* __restrict__ embed,
    const float* __restrict__ WiF, const float* __restrict__ WiB,
    const int* __restrict__ seq)
{
    int d  = blockIdx.z;
    int m0 = blockIdx.y * 64;
    int n0 = blockIdx.x * 128;
    int bb = m0 >> 9, t0 = m0 & 511;
    if (t0 >= __ldg(&seq[bb])) return;   // fully-dead tile (seq_lens sorted desc)

    const float* Wi = d ? WiB : WiF;

    __shared__ unsigned As[1024];
    __shared__ unsigned Bs[2048];

    int tid  = threadIdx.x;
    int lane = tid & 31;
    int wid  = tid >> 5;
    int wm   = wid & 1;
    int wn   = wid >> 1;

    int am = tid >> 2, aq = tid & 3;
    const float* arow = embed + (size_t)g_tok[d][m0 + am] * 512 + aq * 4;
    int a_mt = am >> 4;
    int a_hi = (am >> 3) & 1;
    int a_ln = (am & 7) << 2;

    int bn = tid >> 1, bh = tid & 1;
    const float* brow = Wi + (size_t)(n0 + bn) * 512 + bh * 8;
    int b_nt = bn >> 3;
    int b_ln = (bn & 7) << 2;

    float acc[2][4][4];
#pragma unroll
    for (int i = 0; i < 2; ++i)
#pragma unroll
        for (int j = 0; j < 4; ++j)
#pragma unroll
            for (int q = 0; q < 4; ++q) acc[i][j][q] = 0.f;

    for (int k0 = 0; k0 < 512; k0 += 16) {
        float4 av  = *(const float4*)(arow + k0);
        float4 bv0 = *(const float4*)(brow + k0);
        float4 bv1 = *(const float4*)(brow + k0 + 4);
        __syncthreads();
        {
            float v[4] = {av.x, av.y, av.z, av.w};
#pragma unroll
            for (int e = 0; e < 4; ++e) {
                int kk = aq * 4 + e, k8 = kk >> 3, kl = kk & 7;
                int j = ((kl >> 2) << 1) | a_hi;
                As[(((k8 << 2) + a_mt) << 7) + ((a_ln | (e & 3)) << 2) + j] = tf32r(v[e]);
            }
            float w[8] = {bv0.x, bv0.y, bv0.z, bv0.w, bv1.x, bv1.y, bv1.z, bv1.w};
#pragma unroll
            for (int e = 0; e < 8; ++e) {
                Bs[(((bh << 4) + b_nt) << 6) + ((b_ln | (e & 3)) << 1) + (e >> 2)] = tf32r(w[e]);
            }
        }
        __syncthreads();
#pragma unroll
        for (int k8 = 0; k8 < 2; ++k8) {
            uint4 A0 = *(const uint4*)&As[(((k8 << 2) + wm * 2 + 0) << 7) + (lane << 2)];
            uint4 A1 = *(const uint4*)&As[(((k8 << 2) + wm * 2 + 1) << 7) + (lane << 2)];
#pragma unroll
            for (int j = 0; j < 4; ++j) {
                uint2 Bf = *(const uint2*)&Bs[(((k8 << 4) + wn * 4 + j) << 6) + (lane << 1)];
                MMA_TF32(acc[0][j], A0, Bf.x, Bf.y);
                MMA_TF32(acc[1][j], A1, Bf.x, Bf.y);
            }
        }
    }

    float* C = g_pre[d] + (size_t)m0 * 2048 + n0;
#pragma unroll
    for (int i = 0; i < 2; ++i) {
#pragma unroll
        for (int j = 0; j < 4; ++j) {
            int r0 = wm * 32 + i * 16 + (lane >> 2);
            int c0 = wn * 32 + j * 8 + ((lane & 3) << 1);
            *(float2*)(C + (size_t)r0 * 2048 + c0)       = make_float2(acc[i][j][0], acc[i][j][1]);
            *(float2*)(C + (size_t)(r0 + 8) * 2048 + c0) = make_float2(acc[i][j][2], acc[i][j][3]);
        }
    }
}

// ---------------- persistent recurrence (4 rows/thread, packed f32x2) ----------------
// 128 blocks x 256 threads. block = (dir, 8 hidden units => 32 gate rows).
// warp q (0..7) owns hidden unit j0+q: rows {g*8+q} for gates g=0..3.
// lane owns 16 k (4 floats at kk = lane*4 + m*128, m=0..3). Wh in registers.
__global__ void __launch_bounds__(256, 1) k_rec(
    const float* __restrict__ WhF, const float* __restrict__ WhB,
    const float* __restrict__ bF,  const float* __restrict__ bB,
    const int* __restrict__ seq)
{
    int tid = threadIdx.x;
    int d  = blockIdx.x >> 6;
    int j0 = (blockIdx.x & 63) * 8;
    int q    = tid >> 5;
    int lane = tid & 31;

    const float* Wh = d ? WhB : WhF;
    // w[g][m]: 4 floats of gate-row (g*512 + j0+q) at k = lane*4 + m*128
    ulonglong2 w[4][4];
#pragma unroll
    for (int g = 0; g < 4; ++g)
#pragma unroll
        for (int m = 0; m < 4; ++m)
            w[g][m] = *(const ulonglong2*)(Wh + (size_t)(g * 512 + j0 + q) * 512 + lane * 4 + m * 128);

    const float* bias = d ? bB : bF;
    const float* pre  = g_pre[d];
    float* cptr = g_c[d];

    int a_jj = tid & 7, a_bi = tid >> 3;
    int a_j  = j0 + a_jj;
    float bz0 = 0.f, bz1 = 0.f, bz2 = 0.f, bz3 = 0.f;
    if (tid < 64) {
        bz0 = __ldg(&bias[a_j]);
        bz1 = __ldg(&bias[512 + a_j]);
        bz2 = __ldg(&bias[1024 + a_j]);
        bz3 = __ldg(&bias[1536 + a_j]);
    }

    __shared__ float sh[8][512];
    __shared__ float sdots[32][8];

    int Lmax = __ldg(&seq[0]);

    for (int t = 0; t < Lmax; ++t) {
        int lo = 0, hi = Bn;
        while (lo < hi) { int mid = (lo + hi) >> 1; if (__ldg(&seq[mid]) > t) lo = mid + 1; else hi = mid; }
        int nb = lo;

        const float* hbuf  = g_h[t & 1][d];
        float*       hnext = g_h[(t + 1) & 1][d];

        // prefetch tile 0: 1024 float4 over 256 threads
        float4 pf[4];
#pragma unroll
        for (int p = 0; p < 4; ++p) {
            int f = tid + (p << 8);
            int b = f >> 7; if (b > 63) b = 63;
            pf[p] = __ldcg((const float4*)(hbuf + b * 512 + ((f & 127) << 2)));
        }

        for (int b0 = 0; b0 < nb; b0 += 8) {
            __syncthreads();
#pragma unroll
            for (int p = 0; p < 4; ++p) {
                int f = tid + (p << 8);
                *(float4*)&sh[f >> 7][(f & 127) << 2] = pf[p];
            }
            __syncthreads();

            if (b0 + 8 < nb) {
#pragma unroll
                for (int p = 0; p < 4; ++p) {
                    int f = tid + (p << 8);
                    int b = b0 + 8 + (f >> 7); if (b > 63) b = 63;
                    pf[p] = __ldcg((const float4*)(hbuf + b * 512 + ((f & 127) << 2)));
                }
            }

            // activation-input prefetch (overlaps with dots)
            float pg0 = 0.f, pg1 = 0.f, pg2 = 0.f, pg3 = 0.f, pc = 0.f;
            bool act = (tid < 64) && (b0 + a_bi < nb);
            int ab = b0 + a_bi;
            if (act) {
                size_t pb = ((size_t)(ab << 9) + t) * 2048 + a_j;
                pg0 = pre[pb];
                pg1 = pre[pb + 512];
                pg2 = pre[pb + 1024];
                pg3 = pre[pb + 1536];
                pc  = cptr[(ab << 9) + a_j];
            }

            // dots: 4 gates x 8 batches, 16-k slice per lane, packed FMAs
            unsigned long long acc[4][8];
#pragma unroll
            for (int g = 0; g < 4; ++g)
#pragma unroll
                for (int bi = 0; bi < 8; ++bi) acc[g][bi] = 0ull;
#pragma unroll
            for (int m = 0; m < 4; ++m) {
                int kk = (lane << 2) + (m << 7);
                ulonglong2 w0 = w[0][m], w1 = w[1][m], w2 = w[2][m], w3 = w[3][m];
#pragma unroll
                for (int bi = 0; bi < 8; ++bi) {
                    ulonglong2 hv = *(const ulonglong2*)&sh[bi][kk];
                    FMA2(acc[0][bi], w0.x, hv.x); FMA2(acc[0][bi], w0.y, hv.y);
                    FMA2(acc[1][bi], w1.x, hv.x); FMA2(acc[1][bi], w1.y, hv.y);
                    FMA2(acc[2][bi], w2.x, hv.x); FMA2(acc[2][bi], w2.y, hv.y);
                    FMA2(acc[3][bi], w3.x, hv.x); FMA2(acc[3][bi], w3.y, hv.y);
                }
            }
            // fold lo/hi, pack bi-pairs, xor-butterfly reduce with packed adds
            unsigned long long P[16];
#pragma unroll
            for (int g = 0; g < 4; ++g)
#pragma unroll
                for (int b2 = 0; b2 < 4; ++b2)
                    P[g * 4 + b2] = pack2(fold2(acc[g][b2 * 2]), fold2(acc[g][b2 * 2 + 1]));
#pragma unroll
            for (int off = 16; off; off >>= 1)
#pragma unroll
                for (int i = 0; i < 16; ++i) {
                    unsigned long long o = __shfl_xor_sync(0xffffffffu, P[i], off);
                    ADD2(P[i], P[i], o);
                }
            // every lane now holds all 16 sums; lane i stores pair i
#pragma unroll
            for (int i = 0; i < 16; ++i) {
                if (lane == i) {
                    float l = __uint_as_float((unsigned)(P[i] & 0xffffffffu));
                    float h = __uint_as_float((unsigned)(P[i] >> 32));
                    *(float2*)&sdots[(i >> 2) * 8 + q][(i & 3) << 1] = make_float2(l, h);
                }
            }
            __syncthreads();

            if (act) {
                float gi = pg0 + bz0 + sdots[     a_jj][a_bi];
                float gf = pg1 + bz1 + sdots[ 8 + a_jj][a_bi];
                float gc = pg2 + bz2 + sdots[16 + a_jj][a_bi];
                float go = pg3 + bz3 + sdots[24 + a_jj][a_bi];
                float si = sigf(gi);
                float sf = sigf(gf);
                float so = sigf(go);
                float cn = sf * pc + si * tanhfa(gc);
                float hn = so * tanhfa(cn);
                cptr[(ab << 9) + a_j] = cn;
                __stcg(&hnext[(ab << 9) + a_j], hn);
                int L = __ldg(&seq[ab]);
                int tt = d ? (L - 1 - t) : t;
                g_outH[((size_t)(ab << 9) + tt) * 1024 + (d << 9) + a_j] = hn;
            }
        }

        if (t + 1 < Lmax) {
            __threadfence();
            __syncthreads();
            if (tid == 0) {
                atomicAdd(&g_ctrs[d][t], 1u);
                volatile unsigned* c = &g_ctrs[d][t];
                while (*c < 64u) { }
                __threadfence();
            }
            __syncthreads();
        }
    }
}

// ---------------- feats: warp per (b,t), 12 dots of length 1024 ----------------
__global__ void k_feats(const float* __restrict__ Wout, const float* __restrict__ bout,
                        const int* __restrict__ seq)
{
    int gid  = blockIdx.x * 8 + (threadIdx.x >> 5);
    int lane = threadIdx.x & 31;
    int b = gid >> 9, t = gid & 511;
    if (t >= __ldg(&seq[b])) return;
    const float* orow = g_outH + (size_t)gid * 1024;
    float acc[12];
#pragma unroll
    for (int kk = 0; kk < 12; ++kk) acc[kk] = 0.f;
    for (int k = lane * 4; k < 1024; k += 128) {
        float4 o = *(const float4*)(orow + k);
#pragma unroll
        for (int kk = 0; kk < 12; ++kk) {
            float4 wv = *(const float4*)(Wout + kk * 1024 + k);
            acc[kk] += o.x * wv.x + o.y * wv.y + o.z * wv.z + o.w * wv.w;
        }
    }
#pragma unroll
    for (int kk = 0; kk < 12; ++kk) {
        float v = acc[kk];
#pragma unroll
        for (int off = 16; off; off >>= 1) v += __shfl_down_sync(0xffffffffu, v, off);
        if (lane == 0) g_feats[(size_t)gid * 12 + kk] = v + bout[kk];
    }
}

// ---------------- Viterbi: warp per batch row, lane = tag ----------------
__global__ void k_vit(const float* __restrict__ trans, const int* __restrict__ seq,
                      float* __restrict__ out)
{
    int b = blockIdx.x;
    int lane = threadIdx.x;
    int nx = lane < 12 ? lane : 11;
    float tr[12];
#pragma unroll
    for (int p = 0; p < 12; ++p) tr[p] = trans[nx * 12 + p];
    float fv = (lane < 12 && lane == STARTT) ? 0.f : NEGV;
    int L = seq[b];

    for (int t = 0; t < L; ++t) {
        float m = -1e30f; int arg = 0;
#pragma unroll
        for (int p = 0; p < 12; ++p) {
            float fvp = __shfl_sync(0xffffffffu, fv, p);
            float s = fvp + tr[p];
            if (s > m) { m = s; arg = p; }   // first-index argmax (strict >)
        }
        float ft = g_feats[(size_t)(b * 512 + t) * 12 + nx];
        if (lane < 12) {
            fv = m + ft;
            g_bp[(b * 512 + t) * 12 + lane] = (signed char)arg;
        }
    }

    float term = (lane < 12) ? fv + trans[STOPT * 12 + lane] : -1e30f;
    int idx = lane;
#pragma unroll
    for (int off = 16; off; off >>= 1) {
        float ov = __shfl_down_sync(0xffffffffu, term, off);
        int   oi = __shfl_down_sync(0xffffffffu, idx, off);
        if (ov > term || (ov == term && oi < idx)) { term = ov; idx = oi; }
    }
    if (lane == 0) {
        out[b] = term;
        int carry = idx;
        for (int t = Tn - 1; t >= 0; --t) {
            out[64 + b * 512 + t] = (float)carry;
            if (t < L) carry = g_bp[(b * 512 + t) * 12 + carry];
        }
    }
}

// ---------------- launch ----------------
extern "C" void kernel_launch(void* const* d_in, const int* in_sizes, int n_in,
                              void* d_out, int out_size)
{
    const int*   sent  = (const int*)d_in[0];
    const int*   seq   = (const int*)d_in[1];
    const float* embed = (const float*)d_in[2];
    const float* WiF   = (const float*)d_in[3];
    const float* WhF   = (const float*)d_in[4];
    const float* bF    = (const float*)d_in[5];
    const float* WiB   = (const float*)d_in[6];
    const float* WhB   = (const float*)d_in[7];
    const float* bB    = (const float*)d_in[8];
    const float* h0    = (const float*)d_in[9];
    const float* c0    = (const float*)d_in[10];
    const float* Wout  = (const float*)d_in[11];
    const float* bout  = (const float*)d_in[12];
    const float* trans = (const float*)d_in[13];
    float* out = (float*)d_out;

    k_init<<<(2 * Bn * Hn + 255) / 256, 256>>>(h0, c0);
    k_tok<<<(2 * 32768 + 255) / 256, 256>>>(sent, seq);
    dim3 gg(16, 512, 2);
    k_gemm<<<gg, 256>>>(embed, WiF, WiB, seq);
    k_rec<<<128, 256>>>(WhF, WhB, bF, bB, seq);
    k_feats<<<4096, 256>>>(Wout, bout, seq);
    k_vit<<<64, 32>>>(trans, seq, out);
}

// round 17
// speedup vs baseline: 1.8799x; 1.8799x over previous
#include <cuda_runtime.h>
#include <math.h>

#define Bn 64
#define Tn 512
#define En 512
#define Hn 512
#define Kn 12
#define STARTT 10
#define STOPT 11
#define NEGV (-10000.0f)

// ---------------- scratch (device globals; allocation-free rule) ----------------
__device__ float g_pre[2][32768 * 2048];      // [dir][(b*512+t)*2048 + gate*512+j]
__device__ int   g_tok[2][32768];             // [dir][b*512+t]
__device__ float g_h[2][2][Bn * Hn];          // [phase][dir][b*512+j]
__device__ float g_c[2][Bn * Hn];             // [dir][b*512+j]
__device__ float g_outH[33554432];            // [(b*512+t)*1024 + dir*512+j]
__device__ float g_feats[Bn * Tn * Kn];
__device__ signed char g_bp[Bn * Tn * Kn];
__device__ unsigned g_ctrs[2][Tn];            // per-(dir,step) arrival counters

// ---------------- init ----------------
__global__ void k_init(const float* __restrict__ h0, const float* __restrict__ c0) {
    int i = blockIdx.x * 256 + threadIdx.x;
    if (i < 2 * Tn) ((unsigned*)g_ctrs)[i] = 0u;
    if (i < 2 * Bn * Hn) {
        int d = i / (Bn * Hn), r = i % (Bn * Hn);
        g_h[0][d][r] = h0[i];
        g_c[d][r]    = c0[i];
    }
}

// ---------------- token build (forward + packed-reversed; 0 in padding) ----------------
__global__ void k_tok(const int* __restrict__ sent, const int* __restrict__ seq) {
    int i = blockIdx.x * 256 + threadIdx.x;
    if (i >= 2 * 32768) return;
    int d = i >> 15, r = i & 32767, b = r >> 9, t = r & 511;
    int L = seq[b];
    int tk = 0;
    if (t < L) tk = (d == 0) ? sent[b * Tn + t] : sent[b * Tn + (L - 1 - t)];
    g_tok[d][r] = tk;
}

// ---------------- TF32 helpers ----------------
__device__ __forceinline__ unsigned tf32r(float v) {
    unsigned u;
    asm("cvt.rna.tf32.f32 %0, %1;" : "=r"(u) : "f"(v));
    return u;
}
#define MMA_TF32(c, A, B0, B1)                                                  \
    asm volatile("mma.sync.aligned.m16n8k8.row.col.f32.tf32.tf32.f32 "          \
                 "{%0,%1,%2,%3},{%4,%5,%6,%7},{%8,%9},{%0,%1,%2,%3};"           \
                 : "+f"((c)[0]), "+f"((c)[1]), "+f"((c)[2]), "+f"((c)[3])       \
                 : "r"((A).x), "r"((A).y), "r"((A).z), "r"((A).w),              \
                   "r"(B0), "r"(B1))

__device__ __forceinline__ float sigf(float x) {
    return __fdividef(1.f, 1.f + __expf(-x));
}
__device__ __forceinline__ float tanhfa(float x) {
    return 2.f * __fdividef(1.f, 1.f + __expf(-2.f * x)) - 1.f;
}

// ---------------- input GEMM (TF32 tensor cores): pre = gather(embed, tok) @ Wi^T ----
__global__ void __launch_bounds__(256) k_gemm(
    const float* __restrict__ embed,
    const float* __restrict__ WiF, const float* __restrict__ WiB,
    const int* __restrict__ seq)
{
    int d  = blockIdx.z;
    int m0 = blockIdx.y * 64;
    int n0 = blockIdx.x * 128;
    int bb = m0 >> 9, t0 = m0 & 511;
    if (t0 >= __ldg(&seq[bb])) return;   // fully-dead tile (seq_lens sorted desc)

    const float* Wi = d ? WiB : WiF;

    __shared__ unsigned As[1024];
    __shared__ unsigned Bs[2048];

    int tid  = threadIdx.x;
    int lane = tid & 31;
    int wid  = tid >> 5;
    int wm   = wid & 1;
    int wn   = wid >> 1;

    int am = tid >> 2, aq = tid & 3;
    const float* arow = embed + (size_t)g_tok[d][m0 + am] * 512 + aq * 4;
    int a_mt = am >> 4;
    int a_hi = (am >> 3) & 1;
    int a_ln = (am & 7) << 2;

    int bn = tid >> 1, bh = tid & 1;
    const float* brow = Wi + (size_t)(n0 + bn) * 512 + bh * 8;
    int b_nt = bn >> 3;
    int b_ln = (bn & 7) << 2;

    float acc[2][4][4];
#pragma unroll
    for (int i = 0; i < 2; ++i)
#pragma unroll
        for (int j = 0; j < 4; ++j)
#pragma unroll
            for (int q = 0; q < 4; ++q) acc[i][j][q] = 0.f;

    for (int k0 = 0; k0 < 512; k0 += 16) {
        float4 av  = *(const float4*)(arow + k0);
        float4 bv0 = *(const float4*)(brow + k0);
        float4 bv1 = *(const float4*)(brow + k0 + 4);
        __syncthreads();
        {
            float v[4] = {av.x, av.y, av.z, av.w};
#pragma unroll
            for (int e = 0; e < 4; ++e) {
                int kk = aq * 4 + e, k8 = kk >> 3, kl = kk & 7;
                int j = ((kl >> 2) << 1) | a_hi;
                As[(((k8 << 2) + a_mt) << 7) + ((a_ln | (e & 3)) << 2) + j] = tf32r(v[e]);
            }
            float w[8] = {bv0.x, bv0.y, bv0.z, bv0.w, bv1.x, bv1.y, bv1.z, bv1.w};
#pragma unroll
            for (int e = 0; e < 8; ++e) {
                Bs[(((bh << 4) + b_nt) << 6) + ((b_ln | (e & 3)) << 1) + (e >> 2)] = tf32r(w[e]);
            }
        }
        __syncthreads();
#pragma unroll
        for (int k8 = 0; k8 < 2; ++k8) {
            uint4 A0 = *(const uint4*)&As[(((k8 << 2) + wm * 2 + 0) << 7) + (lane << 2)];
            uint4 A1 = *(const uint4*)&As[(((k8 << 2) + wm * 2 + 1) << 7) + (lane << 2)];
#pragma unroll
            for (int j = 0; j < 4; ++j) {
                uint2 Bf = *(const uint2*)&Bs[(((k8 << 4) + wn * 4 + j) << 6) + (lane << 1)];
                MMA_TF32(acc[0][j], A0, Bf.x, Bf.y);
                MMA_TF32(acc[1][j], A1, Bf.x, Bf.y);
            }
        }
    }

    float* C = g_pre[d] + (size_t)m0 * 2048 + n0;
#pragma unroll
    for (int i = 0; i < 2; ++i) {
#pragma unroll
        for (int j = 0; j < 4; ++j) {
            int r0 = wm * 32 + i * 16 + (lane >> 2);
            int c0 = wn * 32 + j * 8 + ((lane & 3) << 1);
            *(float2*)(C + (size_t)r0 * 2048 + c0)       = make_float2(acc[i][j][0], acc[i][j][1]);
            *(float2*)(C + (size_t)(r0 + 8) * 2048 + c0) = make_float2(acc[i][j][2], acc[i][j][3]);
        }
    }
}

// ---------------- persistent recurrence (tensor-core MMA) ----------------
// 128 blocks x 256 threads. block = (dir, 8 hidden units j0..j0+7) owning 32
// gate-rows {g*512 + j0 + jj} as the N=32 dim, gate-major (n = g*8 + jj).
// 8 warps = (gate-tile ti = wid&3, k-half kh = wid>>2). B (Wh) fragments live
// in registers all 512 steps. A (h) staged in smem, row stride 516 floats
// => A-frag scalar LDS bank = (4*r + c + const) & 31: conflict-free.
#define SH_STRIDE 516
#define SMEM_REC  (64 * SH_STRIDE * 4 + 2 * 4 * 64 * 8 * 4)   // 148480 B

__global__ void __launch_bounds__(256, 1) k_rec(
    const float* __restrict__ WhF, const float* __restrict__ WhB,
    const float* __restrict__ bF,  const float* __restrict__ bB,
    const int* __restrict__ seq)
{
    extern __shared__ unsigned dynsm[];
    unsigned* shA = dynsm;                       // [64][516] tf32 bits
    float*    Cs  = (float*)(dynsm + 64 * SH_STRIDE);  // [2][4][64][8]

    int tid = threadIdx.x;
    int d  = blockIdx.x >> 6;
    int j0 = (blockIdx.x & 63) * 8;
    int lane = tid & 31;
    int wid  = tid >> 5;
    int ti = wid & 3;        // gate tile (n8)
    int kh = wid >> 2;       // k-half (256 each)

    const float* Wh = d ? WhB : WhF;

    // B fragments: 32 k8-tiles x uint2, in registers forever.
    uint2 Bf[32];
    {
        int nloc = lane >> 2, kc = lane & 3;
        const float* wb = Wh + (size_t)(ti * 512 + j0 + nloc) * 512 + kh * 256 + kc;
#pragma unroll
        for (int k8 = 0; k8 < 32; ++k8) {
            Bf[k8].x = tf32r(wb[k8 * 8]);
            Bf[k8].y = tf32r(wb[k8 * 8 + 4]);
        }
    }

    const float* bias = d ? bB : bF;
    const float* pre  = g_pre[d];
    float* cptr = g_c[d];

    int jj = tid & 7;
    int aj = j0 + jj;
    float bz[4];
#pragma unroll
    for (int g = 0; g < 4; ++g) bz[g] = __ldg(&bias[g * 512 + aj]);

    // A-frag per-thread base offset within an m-tile/k8 grid
    int p0 = (lane >> 2) * SH_STRIDE + kh * 256 + (lane & 3);

    int Lmax = __ldg(&seq[0]);

    for (int t = 0; t < Lmax; ++t) {
        // nb = #{b : seq[b] > t}
        int lo = 0, hi = Bn;
        while (lo < hi) { int mid = (lo + hi) >> 1; if (__ldg(&seq[mid]) > t) lo = mid + 1; else hi = mid; }
        int nb = lo;
        int mtn = (nb + 15) >> 4;

        const float* hbuf  = g_h[t & 1][d];
        float*       hnext = g_h[(t + 1) & 1][d];

        // stage h -> shA (tf32 bits), rows [0, nb)
        int nf4 = nb << 7;
        for (int f = tid; f < nf4; f += 256) {
            int b = f >> 7, kq = (f & 127) << 2;
            float4 hv = __ldcg((const float4*)(hbuf + (b << 9) + kq));
            uint4 u;
            u.x = tf32r(hv.x); u.y = tf32r(hv.y); u.z = tf32r(hv.z); u.w = tf32r(hv.w);
            *(uint4*)&shA[b * SH_STRIDE + kq] = u;
        }

        // activation-input prefetch (independent of MMA)
        int bb0 = tid >> 3, bb1 = bb0 + 32;
        bool v0 = bb0 < nb, v1 = bb1 < nb;
        float pg0[4], pg1[4], pc0 = 0.f, pc1 = 0.f;
        if (v0) {
            size_t pb = ((size_t)(bb0 << 9) + t) * 2048 + aj;
#pragma unroll
            for (int g = 0; g < 4; ++g) pg0[g] = pre[pb + g * 512];
            pc0 = cptr[(bb0 << 9) + aj];
        }
        if (v1) {
            size_t pb = ((size_t)(bb1 << 9) + t) * 2048 + aj;
#pragma unroll
            for (int g = 0; g < 4; ++g) pg1[g] = pre[pb + g * 512];
            pc1 = cptr[(bb1 << 9) + aj];
        }
        __syncthreads();   // staging visible

        // MMA: process m-tiles in pairs (two independent accumulator chains)
        for (int mt0 = 0; mt0 < mtn; mt0 += 2) {
            int base0 = mt0 * (16 * SH_STRIDE) + p0;
            if (mt0 + 1 < mtn) {
                float c0[4] = {0.f, 0.f, 0.f, 0.f};
                float c1[4] = {0.f, 0.f, 0.f, 0.f};
#pragma unroll
                for (int k8 = 0; k8 < 32; ++k8) {
                    int o = base0 + k8 * 8;
                    uint4 A0, A1;
                    A0.x = shA[o];
                    A0.y = shA[o + 8 * SH_STRIDE];
                    A0.z = shA[o + 4];
                    A0.w = shA[o + 8 * SH_STRIDE + 4];
                    int o1 = o + 16 * SH_STRIDE;
                    A1.x = shA[o1];
                    A1.y = shA[o1 + 8 * SH_STRIDE];
                    A1.z = shA[o1 + 4];
                    A1.w = shA[o1 + 8 * SH_STRIDE + 4];
                    MMA_TF32(c0, A0, Bf[k8].x, Bf[k8].y);
                    MMA_TF32(c1, A1, Bf[k8].x, Bf[k8].y);
                }
                int row = mt0 * 16 + (lane >> 2);
                int cb  = ((kh * 4 + ti) << 9) + ((lane & 3) << 1);
                *(float2*)&Cs[cb + (row << 3)]        = make_float2(c0[0], c0[1]);
                *(float2*)&Cs[cb + ((row + 8) << 3)]  = make_float2(c0[2], c0[3]);
                *(float2*)&Cs[cb + ((row + 16) << 3)] = make_float2(c1[0], c1[1]);
                *(float2*)&Cs[cb + ((row + 24) << 3)] = make_float2(c1[2], c1[3]);
            } else {
                float c0[4] = {0.f, 0.f, 0.f, 0.f};
#pragma unroll
                for (int k8 = 0; k8 < 32; ++k8) {
                    int o = base0 + k8 * 8;
                    uint4 A0;
                    A0.x = shA[o];
                    A0.y = shA[o + 8 * SH_STRIDE];
                    A0.z = shA[o + 4];
                    A0.w = shA[o + 8 * SH_STRIDE + 4];
                    MMA_TF32(c0, A0, Bf[k8].x, Bf[k8].y);
                }
                int row = mt0 * 16 + (lane >> 2);
                int cb  = ((kh * 4 + ti) << 9) + ((lane & 3) << 1);
                *(float2*)&Cs[cb + (row << 3)]       = make_float2(c0[0], c0[1]);
                *(float2*)&Cs[cb + ((row + 8) << 3)] = make_float2(c0[2], c0[3]);
            }
        }
        __syncthreads();   // Cs ready

        // activations: thread = (bb, jj); combine the two k-half partials
        if (v0) {
            int cbase = (bb0 << 3) + jj;
            float gi = pg0[0] + bz[0] + Cs[cbase]           + Cs[cbase + 2048];
            float gf = pg0[1] + bz[1] + Cs[cbase + 512]     + Cs[cbase + 2560];
            float gc = pg0[2] + bz[2] + Cs[cbase + 1024]    + Cs[cbase + 3072];
            float go = pg0[3] + bz[3] + Cs[cbase + 1536]    + Cs[cbase + 3584];
            float si = sigf(gi), sf = sigf(gf), so = sigf(go);
            float cn = sf * pc0 + si * tanhfa(gc);
            float hn = so * tanhfa(cn);
            cptr[(bb0 << 9) + aj] = cn;
            __stcg(&hnext[(bb0 << 9) + aj], hn);
            int L = __ldg(&seq[bb0]);
            int tt = d ? (L - 1 - t) : t;
            g_outH[((size_t)(bb0 << 9) + tt) * 1024 + (d << 9) + aj] = hn;
        }
        if (v1) {
            int cbase = (bb1 << 3) + jj;
            float gi = pg1[0] + bz[0] + Cs[cbase]           + Cs[cbase + 2048];
            float gf = pg1[1] + bz[1] + Cs[cbase + 512]     + Cs[cbase + 2560];
            float gc = pg1[2] + bz[2] + Cs[cbase + 1024]    + Cs[cbase + 3072];
            float go = pg1[3] + bz[3] + Cs[cbase + 1536]    + Cs[cbase + 3584];
            float si = sigf(gi), sf = sigf(gf), so = sigf(go);
            float cn = sf * pc1 + si * tanhfa(gc);
            float hn = so * tanhfa(cn);
            cptr[(bb1 << 9) + aj] = cn;
            __stcg(&hnext[(bb1 << 9) + aj], hn);
            int L = __ldg(&seq[bb1]);
            int tt = d ? (L - 1 - t) : t;
            g_outH[((size_t)(bb1 << 9) + tt) * 1024 + (d << 9) + aj] = hn;
        }

        // per-dir grid barrier (64 blocks), skipped on the final step
        if (t + 1 < Lmax) {
            __threadfence();
            __syncthreads();
            if (tid == 0) {
                atomicAdd(&g_ctrs[d][t], 1u);
                volatile unsigned* c = &g_ctrs[d][t];
                while (*c < 64u) { }
                __threadfence();
            }
            __syncthreads();
        }
    }
}

// ---------------- feats: warp per (b,t), 12 dots of length 1024 ----------------
__global__ void k_feats(const float* __restrict__ Wout, const float* __restrict__ bout,
                        const int* __restrict__ seq)
{
    int gid  = blockIdx.x * 8 + (threadIdx.x >> 5);
    int lane = threadIdx.x & 31;
    int b = gid >> 9, t = gid & 511;
    if (t >= __ldg(&seq[b])) return;
    const float* orow = g_outH + (size_t)gid * 1024;
    float acc[12];
#pragma unroll
    for (int kk = 0; kk < 12; ++kk) acc[kk] = 0.f;
    for (int k = lane * 4; k < 1024; k += 128) {
        float4 o = *(const float4*)(orow + k);
#pragma unroll
        for (int kk = 0; kk < 12; ++kk) {
            float4 wv = *(const float4*)(Wout + kk * 1024 + k);
            acc[kk] += o.x * wv.x + o.y * wv.y + o.z * wv.z + o.w * wv.w;
        }
    }
#pragma unroll
    for (int kk = 0; kk < 12; ++kk) {
        float v = acc[kk];
#pragma unroll
        for (int off = 16; off; off >>= 1) v += __shfl_down_sync(0xffffffffu, v, off);
        if (lane == 0) g_feats[(size_t)gid * 12 + kk] = v + bout[kk];
    }
}

// ---------------- Viterbi: warp per batch row, lane = tag ----------------
__global__ void k_vit(const float* __restrict__ trans, const int* __restrict__ seq,
                      float* __restrict__ out)
{
    int b = blockIdx.x;
    int lane = threadIdx.x;
    int nx = lane < 12 ? lane : 11;
    float tr[12];
#pragma unroll
    for (int p = 0; p < 12; ++p) tr[p] = trans[nx * 12 + p];
    float fv = (lane < 12 && lane == STARTT) ? 0.f : NEGV;
    int L = seq[b];

    for (int t = 0; t < L; ++t) {
        float m = -1e30f; int arg = 0;
#pragma unroll
        for (int p = 0; p < 12; ++p) {
            float fvp = __shfl_sync(0xffffffffu, fv, p);
            float s = fvp + tr[p];
            if (s > m) { m = s; arg = p; }   // first-index argmax (strict >)
        }
        float ft = g_feats[(size_t)(b * 512 + t) * 12 + nx];
        if (lane < 12) {
            fv = m + ft;
            g_bp[(b * 512 + t) * 12 + lane] = (signed char)arg;
        }
    }

    float term = (lane < 12) ? fv + trans[STOPT * 12 + lane] : -1e30f;
    int idx = lane;
#pragma unroll
    for (int off = 16; off; off >>= 1) {
        float ov = __shfl_down_sync(0xffffffffu, term, off);
        int   oi = __shfl_down_sync(0xffffffffu, idx, off);
        if (ov > term || (ov == term && oi < idx)) { term = ov; idx = oi; }
    }
    if (lane == 0) {
        out[b] = term;
        int carry = idx;
        for (int t = Tn - 1; t >= 0; --t) {
            out[64 + b * 512 + t] = (float)carry;
            if (t < L) carry = g_bp[(b * 512 + t) * 12 + carry];
        }
    }
}

// ---------------- launch ----------------
extern "C" void kernel_launch(void* const* d_in, const int* in_sizes, int n_in,
                              void* d_out, int out_size)
{
    const int*   sent  = (const int*)d_in[0];
    const int*   seq   = (const int*)d_in[1];
    const float* embed = (const float*)d_in[2];
    const float* WiF   = (const float*)d_in[3];
    const float* WhF   = (const float*)d_in[4];
    const float* bF    = (const float*)d_in[5];
    const float* WiB   = (const float*)d_in[6];
    const float* WhB   = (const float*)d_in[7];
    const float* bB    = (const float*)d_in[8];
    const float* h0    = (const float*)d_in[9];
    const float* c0    = (const float*)d_in[10];
    const float* Wout  = (const float*)d_in[11];
    const float* bout  = (const float*)d_in[12];
    const float* trans = (const float*)d_in[13];
    float* out = (float*)d_out;

    cudaFuncSetAttribute(k_rec, cudaFuncAttributeMaxDynamicSharedMemorySize, SMEM_REC);

    k_init<<<(2 * Bn * Hn + 255) / 256, 256>>>(h0, c0);
    k_tok<<<(2 * 32768 + 255) / 256, 256>>>(sent, seq);
    dim3 gg(16, 512, 2);
    k_gemm<<<gg, 256>>>(embed, WiF, WiB, seq);
    k_rec<<<128, 256, SMEM_REC>>>(WhF, WhB, bF, bB, seq);
    k_feats<<<4096, 256>>>(Wout, bout, seq);
    k_vit<<<64, 32>>>(trans, seq, out);
}